// round 16
// baseline (speedup 1.0000x reference)
#include <cuda_runtime.h>
#include <cuda_bf16.h>
#include <cuda_fp16.h>
#include <math.h>
#include <stdint.h>

// Problem constants
#define B     4
#define N     2048
#define D     512
#define HEADS 8
#define DH    64
#define INNER 512
#define M_ROWS (B*N)        // 8192
#define KU512  (512/2)      // 256 u32 (fp16 pairs) per row of K=512

// Band params
#define BW 64
#define RB 64

// GEMM smem geometry (u32 units) — 64-fp16 k-chunk per stage, 3 stages
#define KCHUNK    32                    // u32 per row per stage (64 fp16)
#define ROWSTRIDE 36                    // 32 payload + 4 pad (cp.async + ldmatrix conflict-free)
#define ARR_U32   (128 * ROWSTRIDE)     // 4608 u32 per array
#define STAGE2_U32 (2 * ARR_U32)        // A + B = 36KB per stage
#define NSTAGES   3
#define GEMM2_SMEM_BYTES (NSTAGES * STAGE2_U32 * 4)  // 110592 (108KB)

// ---------------- scratch (__device__ globals; no allocation) ----------------
__device__ uint32_t g_x16[M_ROWS * KU512];     // x fp16 pairs
__device__ uint32_t g_wvt16[INNER * KU512];    // W_v^T fp16 pairs
__device__ uint32_t g_wot16[D * (INNER/2)];    // W_out^T fp16 pairs
__device__ float    g_v[M_ROWS * INNER];
__device__ unsigned short g_a16[M_ROWS * INNER]; // attn fp16
__device__ float    g_inv[B*HEADS*N];

// ---------------- helpers ----------------
__device__ __forceinline__ void mma_fp16(float& d0, float& d1, float& d2, float& d3,
                                         uint32_t a0, uint32_t a1, uint32_t a2, uint32_t a3,
                                         uint32_t b0, uint32_t b1) {
    asm volatile(
        "mma.sync.aligned.m16n8k16.row.col.f32.f16.f16.f32 "
        "{%0,%1,%2,%3}, {%4,%5,%6,%7}, {%8,%9}, {%0,%1,%2,%3};\n"
        : "+f"(d0), "+f"(d1), "+f"(d2), "+f"(d3)
        : "r"(a0), "r"(a1), "r"(a2), "r"(a3), "r"(b0), "r"(b1));
}

__device__ __forceinline__ void ldsm_x4(uint32_t& r0, uint32_t& r1, uint32_t& r2, uint32_t& r3,
                                        uint32_t addr) {
    asm volatile("ldmatrix.sync.aligned.m8n8.x4.shared.b16 {%0,%1,%2,%3}, [%4];\n"
                 : "=r"(r0), "=r"(r1), "=r"(r2), "=r"(r3) : "r"(addr));
}

__device__ __forceinline__ void cp_async16(uint32_t* smem, const uint32_t* gmem) {
    uint32_t s = (uint32_t)__cvta_generic_to_shared(smem);
    asm volatile("cp.async.cg.shared.global [%0], [%1], 16;\n" :: "r"(s), "l"(gmem));
}
__device__ __forceinline__ void cp_commit() { asm volatile("cp.async.commit_group;\n"); }
__device__ __forceinline__ void cp_wait2()  { asm volatile("cp.async.wait_group 2;\n"); }
__device__ __forceinline__ void cp_wait1()  { asm volatile("cp.async.wait_group 1;\n"); }
__device__ __forceinline__ void cp_wait0()  { asm volatile("cp.async.wait_group 0;\n"); }

// ---------------- packed f32x2 (Blackwell base ISA) ----------------
__device__ __forceinline__ uint64_t f32x2_pack(float lo, float hi) {
    float2 t = make_float2(lo, hi);
    return *reinterpret_cast<uint64_t*>(&t);
}
__device__ __forceinline__ float2 f32x2_unpack(uint64_t v) {
    return *reinterpret_cast<float2*>(&v);
}
__device__ __forceinline__ uint64_t fma2(uint64_t a, uint64_t b, uint64_t c) {
    uint64_t d;
    asm("fma.rn.f32x2 %0, %1, %2, %3;" : "=l"(d) : "l"(a), "l"(b), "l"(c));
    return d;
}
__device__ __forceinline__ uint64_t mul2(uint64_t a, uint64_t b) {
    uint64_t d;
    asm("mul.rn.f32x2 %0, %1, %2;" : "=l"(d) : "l"(a), "l"(b));
    return d;
}

// ============================================================
// convert_both: transpose-convert W_v AND W_out in one launch.
// grid.z = 0 -> W_v [D][INNER] -> wvt16 [INNER][D/2]
// grid.z = 1 -> W_out [INNER][D] -> wot16 [D][INNER/2]
// ============================================================
__global__ __launch_bounds__(256)
void convert_both_kernel(const float* __restrict__ Wv, uint32_t* __restrict__ Wv16,
                         const float* __restrict__ Wo, uint32_t* __restrict__ Wo16)
{
    const float* W = (blockIdx.z == 0) ? Wv : Wo;
    uint32_t* W16  = (blockIdx.z == 0) ? Wv16 : Wo16;
    const int K  = 512, Nc = 512;   // both square here

    __shared__ float s[32][33];
    const int k0 = blockIdx.y * 32, n0 = blockIdx.x * 32;
    const int tx = threadIdx.x & 31, ty = threadIdx.x >> 5;
    #pragma unroll
    for (int q = 0; q < 4; q++)
        s[ty + 8*q][tx] = W[(size_t)(k0 + ty + 8*q) * Nc + n0 + tx];
    __syncthreads();
    for (int o = threadIdx.x; o < 512; o += 256) {
        const int n  = o >> 4;
        const int kp = o & 15;
        __half2 hp = __floats2half2_rn(s[2*kp][n], s[2*kp + 1][n]);
        size_t oi = (size_t)(n0 + n) * (K >> 1) + (k0 >> 1) + kp;
        W16[oi] = *reinterpret_cast<uint32_t*>(&hp);
    }
}

// ============================================================
// fp16 1-pass GEMM: C = A(fp16) @ B16^T (+bias if non-null).
// 64-fp16 k-chunk per stage, 3-stage cp.async pipeline (prefetch
// distance 2 ~ 1200cyc load cover), ldmatrix fragments.
// ============================================================
__global__ __launch_bounds__(256, 2)
void gemm_a16_1p_kernel(const uint32_t* __restrict__ A16, const uint32_t* __restrict__ B16,
                        const float* __restrict__ bias, float* __restrict__ C,
                        int Ncols, int K)
{
    extern __shared__ uint32_t smem[];
    const int KUr = K >> 1;
    const int ntiles = KUr >> 5;          // KCHUNK=32 u32 per tile

    const int tid = threadIdx.x;
    const int wid = tid >> 5, lane = tid & 31;
    const int warp_m = wid & 1;
    const int warp_n = wid >> 1;
    const int r  = lane >> 2;
    const int cq = lane & 3;
    const int rowBase = blockIdx.y * 128;
    const int colBase = blockIdx.x * 128;

    const int ldRow = tid >> 3;           // base row, j-steps of 32
    const int ldC16 = tid & 7;

    const int aOffBase = (warp_m * 64 + (lane & 15)) * ROWSTRIDE + ((lane >> 4) << 2);
    const int bOffBase = (warp_n * 32 + (lane & 7) + ((lane >> 4) << 3)) * ROWSTRIDE
                         + (((lane >> 3) & 1) << 2);

    const uint32_t smem_base_addr = (uint32_t)__cvta_generic_to_shared(smem);

    #define PREFETCH2(kt, st) do {                                                    \
        uint32_t* s_ = smem + (st) * STAGE2_U32;                                      \
        _Pragma("unroll")                                                             \
        for (int j = 0; j < 4; j++) {                                                 \
            const int row_ = ldRow + j * 32;                                          \
            const int cu_  = ldC16 * 4;                                               \
            const size_t ao_ = (size_t)(rowBase + row_) * KUr + (kt) + cu_;           \
            const size_t bo_ = (size_t)(colBase + row_) * KUr + (kt) + cu_;           \
            cp_async16(s_ + 0*ARR_U32 + row_*ROWSTRIDE + cu_, A16 + ao_);             \
            cp_async16(s_ + 1*ARR_U32 + row_*ROWSTRIDE + cu_, B16 + bo_);             \
        }                                                                             \
    } while (0)

    float acc[4][4][4];
    #pragma unroll
    for (int a = 0; a < 4; a++)
        #pragma unroll
        for (int b_ = 0; b_ < 4; b_++)
            #pragma unroll
            for (int c = 0; c < 4; c++) acc[a][b_][c] = 0.f;

    // prologue: prefetch tiles 0 and 1
    PREFETCH2(0, 0);
    cp_commit();
    if (ntiles > 1) {
        PREFETCH2(KCHUNK, 1);
        cp_commit();
    }

    int st = 0;                 // stage of tile t
    for (int t = 0; t < ntiles; t++) {
        // prefetch t+2 into the buffer freed by tile t-1
        if (t + 2 < ntiles) {
            int st2 = st + 2; if (st2 >= NSTAGES) st2 -= NSTAGES;
            PREFETCH2((t + 2) * KCHUNK, st2);
            cp_commit();
        }
        // ensure tile t's group is complete (groups newer than t: count)
        if (t + 2 < ntiles)      cp_wait2();
        else if (t + 1 < ntiles) cp_wait1();
        else                     cp_wait0();
        __syncthreads();

        const uint32_t stage = smem_base_addr + (st * STAGE2_U32) * 4;
        const uint32_t aB  = stage + (0 * ARR_U32 + aOffBase) * 4;
        const uint32_t bB  = stage + (1 * ARR_U32 + bOffBase) * 4;

        #pragma unroll
        for (int ks = 0; ks < 4; ks++) {
            const uint32_t kuB = ks * 8 * 4;
            uint32_t bh[4][2];
            #pragma unroll
            for (int pair = 0; pair < 2; pair++) {
                const uint32_t po = pair * 16 * ROWSTRIDE * 4;
                ldsm_x4(bh[2*pair][0], bh[2*pair][1], bh[2*pair+1][0], bh[2*pair+1][1],
                        bB + po + kuB);
            }
            #pragma unroll
            for (int mt = 0; mt < 4; mt++) {
                const uint32_t mo = mt * 16 * ROWSTRIDE * 4;
                uint32_t a0, a1, a2, a3;
                ldsm_x4(a0, a1, a2, a3, aB + mo + kuB);
                #pragma unroll
                for (int nt = 0; nt < 4; nt++) {
                    float* d = acc[mt][nt];
                    mma_fp16(d[0], d[1], d[2], d[3], a0, a1, a2, a3, bh[nt][0], bh[nt][1]);
                }
            }
        }
        __syncthreads();

        if (++st >= NSTAGES) st = 0;
    }
    #undef PREFETCH2

    #pragma unroll
    for (int mt = 0; mt < 4; mt++) {
        const int row0 = rowBase + warp_m * 64 + mt * 16 + r;
        #pragma unroll
        for (int nt = 0; nt < 4; nt++) {
            const int col = colBase + warp_n * 32 + nt * 8 + 2 * cq;
            float b0v = 0.f, b1v = 0.f;
            if (bias) { b0v = bias[col]; b1v = bias[col + 1]; }
            float2 p0 = make_float2(acc[mt][nt][0] + b0v, acc[mt][nt][1] + b1v);
            float2 p1 = make_float2(acc[mt][nt][2] + b0v, acc[mt][nt][3] + b1v);
            *(float2*)&C[(size_t)row0 * Ncols + col]       = p0;
            *(float2*)&C[(size_t)(row0 + 8) * Ncols + col] = p1;
        }
    }
}

// ============================================================
// sigma + x->fp16 fused: one warp per (b,n) row.
// ============================================================
__global__ __launch_bounds__(256)
void sigma_x16_kernel(const float* __restrict__ x, const float4* __restrict__ Wsig,
                      const float* __restrict__ bsig, float* __restrict__ inv_out,
                      uint32_t* __restrict__ x16)
{
    const int warp = threadIdx.x >> 5;
    const int lane = threadIdx.x & 31;
    const int bn = blockIdx.x * 8 + warp;
    const int b = bn / N;
    const int n = bn % N;

    const float2* xrow = (const float2*)(x + (size_t)bn * D);
    uint32_t* xout = x16 + (size_t)bn * KU512;

    float acc[HEADS];
    #pragma unroll
    for (int h = 0; h < HEADS; h++) acc[h] = 0.f;

    #pragma unroll
    for (int it = 0; it < D / 64; it++) {
        const int p = lane + 32 * it;
        const float2 xv = __ldg(&xrow[p]);
        const float4 wa0 = __ldg(&Wsig[(2*p) * 2 + 0]);
        const float4 wa1 = __ldg(&Wsig[(2*p) * 2 + 1]);
        const float4 wb0 = __ldg(&Wsig[(2*p + 1) * 2 + 0]);
        const float4 wb1 = __ldg(&Wsig[(2*p + 1) * 2 + 1]);
        acc[0] += xv.x * wa0.x + xv.y * wb0.x;
        acc[1] += xv.x * wa0.y + xv.y * wb0.y;
        acc[2] += xv.x * wa0.z + xv.y * wb0.z;
        acc[3] += xv.x * wa0.w + xv.y * wb0.w;
        acc[4] += xv.x * wa1.x + xv.y * wb1.x;
        acc[5] += xv.x * wa1.y + xv.y * wb1.y;
        acc[6] += xv.x * wa1.z + xv.y * wb1.z;
        acc[7] += xv.x * wa1.w + xv.y * wb1.w;
        __half2 hp = __floats2half2_rn(xv.x, xv.y);
        xout[p] = *reinterpret_cast<uint32_t*>(&hp);
    }

    #pragma unroll
    for (int off = 16; off > 0; off >>= 1)
        #pragma unroll
        for (int h = 0; h < HEADS; h++)
            acc[h] += __shfl_xor_sync(0xFFFFFFFFu, acc[h], off);

    if (lane < HEADS) {
        const int h = lane;
        float s = acc[h] + __ldg(&bsig[h]);
        float sig = 1.f / (1.f + expf(-s));
        float denom = expf(sig) + 1.f;
        inv_out[((size_t)b * HEADS + h) * N + n] = 1.f / denom;
    }
}

// ============================================================
// Band kernel — f32x2 Horner, 8 rows/thread (256 threads).
// ============================================================
__global__ __launch_bounds__(256)
void band_kernel(const float* __restrict__ v, const float* __restrict__ inv_arr,
                 unsigned short* __restrict__ a16)
{
    __shared__ float vs[RB + 2 * BW][DH];   // 192 x 64 = 48KB

    const int b  = blockIdx.z;
    const int h  = blockIdx.y;
    const int i0 = blockIdx.x * RB;
    const int tid = threadIdx.x;
    const int lp  = tid & 31;
    const int g   = tid >> 5;

    for (int t = tid; t < (RB + 2 * BW) * (DH / 4); t += 256) {
        const int row = t >> 4;
        const int c4  = (t & 15) * 4;
        const int jj  = i0 - BW + row;
        float4 val = make_float4(0.f, 0.f, 0.f, 0.f);
        if (jj >= 0 && jj < N)
            val = __ldg((const float4*)&v[((size_t)(b * N + jj)) * INNER + h * DH + c4]);
        *(float4*)&vs[row][c4] = val;
    }
    __syncthreads();

    const float* invp = inv_arr + ((size_t)b * HEADS + h) * N;
    const int base = i0 + g * 8;

    float rr[8], iv[8];
    uint64_t rr2[8], accL[8], accR[8];
    #pragma unroll
    for (int t = 0; t < 8; t++) {
        iv[t]   = invp[base + t];
        rr[t]   = __expf(-iv[t]);
        rr2[t]  = f32x2_pack(rr[t], rr[t]);
        accL[t] = 0ull;
        accR[t] = 0ull;
    }

    // Left sweep: j ascending; center included.
    {
        int jl = g * 8;
        #pragma unroll 8
        for (int m = 0; m < 65; m++) {
            const uint64_t v2 = *(const uint64_t*)&vs[jl][2 * lp];
            #pragma unroll
            for (int t = 0; t < 8; t++) accL[t] = fma2(accL[t], rr2[t], v2);
            jl++;
        }
        #pragma unroll
        for (int m = 65; m < 72; m++) {
            const uint64_t v2 = *(const uint64_t*)&vs[jl][2 * lp];
            #pragma unroll
            for (int t = 0; t < 8; t++)
                if (t >= m - 64) accL[t] = fma2(accL[t], rr2[t], v2);
            jl++;
        }
    }

    // Right sweep: j descending, windows [center+1, center+64].
    {
        int jl = g * 8 + 135;
        #pragma unroll 8
        for (int m = 0; m < 64; m++) {
            const uint64_t v2 = *(const uint64_t*)&vs[jl][2 * lp];
            #pragma unroll
            for (int t = 0; t < 8; t++) accR[t] = fma2(accR[t], rr2[t], v2);
            jl--;
        }
        #pragma unroll
        for (int m = 64; m < 71; m++) {
            const uint64_t v2 = *(const uint64_t*)&vs[jl][2 * lp];
            #pragma unroll
            for (int t = 0; t < 8; t++)
                if (t <= 70 - m) accR[t] = fma2(accR[t], rr2[t], v2);
            jl--;
        }
    }

    // combine, normalize (exact analytic Z), emit fp16 pair
    #pragma unroll
    for (int t = 0; t < 8; t++) {
        const int i = base + t;
        const float r_ = rr[t];
        const uint64_t sum2 = fma2(rr2[t], accR[t], accL[t]);
        const float Z = (1.f - __expf(-(float)(i + 1) * iv[t])
                         + r_ - __expf(-(float)(N - i) * iv[t])) / (1.f - r_);
        const float zi = 1.f / Z;
        const float2 o = f32x2_unpack(mul2(sum2, f32x2_pack(zi, zi)));

        __half2 hp = __halves2half2(__float2half_rn(o.x), __float2half_rn(o.y));
        const size_t idx = ((size_t)(b * N + i)) * INNER + h * DH + 2 * lp;
        *(uint32_t*)&a16[idx] = *reinterpret_cast<uint32_t*>(&hp);
    }
}

// ============================================================
// Launch: x, W_v, W_sigma, b_sigma, W_out, b_out
// ============================================================
extern "C" void kernel_launch(void* const* d_in, const int* in_sizes, int n_in,
                              void* d_out, int out_size)
{
    const float* x     = (const float*)d_in[0];
    const float* W_v   = (const float*)d_in[1];
    const float* W_sig = (const float*)d_in[2];
    const float* b_sig = (const float*)d_in[3];
    const float* W_out = (const float*)d_in[4];
    const float* b_out = (const float*)d_in[5];
    float* out = (float*)d_out;

    uint32_t *x16, *wvt16, *wot16;
    float *v, *inv;
    unsigned short *a16;
    cudaGetSymbolAddress((void**)&x16, g_x16);
    cudaGetSymbolAddress((void**)&wvt16, g_wvt16);
    cudaGetSymbolAddress((void**)&wot16, g_wot16);
    cudaGetSymbolAddress((void**)&v, g_v);
    cudaGetSymbolAddress((void**)&inv, g_inv);
    cudaGetSymbolAddress((void**)&a16, g_a16);

    static bool attr_set = false;
    if (!attr_set) {
        cudaFuncSetAttribute(gemm_a16_1p_kernel,
                             cudaFuncAttributeMaxDynamicSharedMemorySize,
                             GEMM2_SMEM_BYTES);
        attr_set = true;
    }

    // both weight transposes in ONE launch
    {
        dim3 grid(16, 16, 2);
        convert_both_kernel<<<grid, 256>>>(W_v, wvt16, W_out, wot16);
    }
    // sigma + x->fp16 (fused)
    sigma_x16_kernel<<<M_ROWS / 8, 256>>>(x, (const float4*)W_sig, b_sig, inv, x16);
    // v = x @ W_v  (fp16 1-pass, 3-stage)
    {
        dim3 grid(INNER / 128, M_ROWS / 128);
        gemm_a16_1p_kernel<<<grid, 256, GEMM2_SMEM_BYTES>>>(x16, wvt16, nullptr, v,
                                                            INNER, D);
    }
    // banded prior @ v -> attn fp16
    {
        dim3 grid(N / RB, HEADS, B);
        band_kernel<<<grid, 256>>>(v, inv, a16);
    }
    // out = attn @ W_out + b_out  (fp16 1-pass, 3-stage)
    {
        dim3 grid(D / 128, M_ROWS / 128);
        gemm_a16_1p_kernel<<<grid, 256, GEMM2_SMEM_BYTES>>>((const uint32_t*)a16,
                                                            wot16, b_out, out,
                                                            D, INNER);
    }
}

// round 17
// speedup vs baseline: 1.0952x; 1.0952x over previous
#include <cuda_runtime.h>
#include <cuda_bf16.h>
#include <cuda_fp16.h>
#include <math.h>
#include <stdint.h>

// Problem constants
#define B     4
#define N     2048
#define D     512
#define HEADS 8
#define DH    64
#define INNER 512
#define M_ROWS (B*N)        // 8192
#define KU512  (512/2)      // 256 u32 (fp16 pairs) per row of K=512

// Band params — BW=40: tail weight r^41 <= 1.6e-5, rel err add <= ~2e-5
#define BW 40
#define RB 64

// GEMM smem geometry (u32 units) — 64-fp16 k-chunk per stage, 3 stages
#define KCHUNK    32                    // u32 per row per stage (64 fp16)
#define ROWSTRIDE 36                    // 32 payload + 4 pad (cp.async + ldmatrix conflict-free)
#define ARR_U32   (128 * ROWSTRIDE)     // 4608 u32 per array
#define STAGE2_U32 (2 * ARR_U32)        // A + B = 36KB per stage
#define NSTAGES   3
#define GEMM2_SMEM_BYTES (NSTAGES * STAGE2_U32 * 4)  // 110592 (108KB)

// ---------------- scratch (__device__ globals; no allocation) ----------------
__device__ uint32_t g_x16[M_ROWS * KU512];     // x fp16 pairs
__device__ uint32_t g_wvt16[INNER * KU512];    // W_v^T fp16 pairs
__device__ uint32_t g_wot16[D * (INNER/2)];    // W_out^T fp16 pairs
__device__ float    g_v[M_ROWS * INNER];
__device__ unsigned short g_a16[M_ROWS * INNER]; // attn fp16
__device__ float    g_inv[B*HEADS*N];

// ---------------- helpers ----------------
__device__ __forceinline__ void mma_fp16(float& d0, float& d1, float& d2, float& d3,
                                         uint32_t a0, uint32_t a1, uint32_t a2, uint32_t a3,
                                         uint32_t b0, uint32_t b1) {
    asm volatile(
        "mma.sync.aligned.m16n8k16.row.col.f32.f16.f16.f32 "
        "{%0,%1,%2,%3}, {%4,%5,%6,%7}, {%8,%9}, {%0,%1,%2,%3};\n"
        : "+f"(d0), "+f"(d1), "+f"(d2), "+f"(d3)
        : "r"(a0), "r"(a1), "r"(a2), "r"(a3), "r"(b0), "r"(b1));
}

__device__ __forceinline__ void ldsm_x4(uint32_t& r0, uint32_t& r1, uint32_t& r2, uint32_t& r3,
                                        uint32_t addr) {
    asm volatile("ldmatrix.sync.aligned.m8n8.x4.shared.b16 {%0,%1,%2,%3}, [%4];\n"
                 : "=r"(r0), "=r"(r1), "=r"(r2), "=r"(r3) : "r"(addr));
}

__device__ __forceinline__ void cp_async16(uint32_t* smem, const uint32_t* gmem) {
    uint32_t s = (uint32_t)__cvta_generic_to_shared(smem);
    asm volatile("cp.async.cg.shared.global [%0], [%1], 16;\n" :: "r"(s), "l"(gmem));
}
__device__ __forceinline__ void cp_commit() { asm volatile("cp.async.commit_group;\n"); }
__device__ __forceinline__ void cp_wait2()  { asm volatile("cp.async.wait_group 2;\n"); }
__device__ __forceinline__ void cp_wait1()  { asm volatile("cp.async.wait_group 1;\n"); }
__device__ __forceinline__ void cp_wait0()  { asm volatile("cp.async.wait_group 0;\n"); }

// ---------------- packed f32x2 (Blackwell base ISA) ----------------
__device__ __forceinline__ uint64_t f32x2_pack(float lo, float hi) {
    float2 t = make_float2(lo, hi);
    return *reinterpret_cast<uint64_t*>(&t);
}
__device__ __forceinline__ float2 f32x2_unpack(uint64_t v) {
    return *reinterpret_cast<float2*>(&v);
}
__device__ __forceinline__ uint64_t fma2(uint64_t a, uint64_t b, uint64_t c) {
    uint64_t d;
    asm("fma.rn.f32x2 %0, %1, %2, %3;" : "=l"(d) : "l"(a), "l"(b), "l"(c));
    return d;
}
__device__ __forceinline__ uint64_t mul2(uint64_t a, uint64_t b) {
    uint64_t d;
    asm("mul.rn.f32x2 %0, %1, %2;" : "=l"(d) : "l"(a), "l"(b));
    return d;
}

// ============================================================
// convert_both: transpose-convert W_v AND W_out in one launch.
// ============================================================
__global__ __launch_bounds__(256)
void convert_both_kernel(const float* __restrict__ Wv, uint32_t* __restrict__ Wv16,
                         const float* __restrict__ Wo, uint32_t* __restrict__ Wo16)
{
    const float* W = (blockIdx.z == 0) ? Wv : Wo;
    uint32_t* W16  = (blockIdx.z == 0) ? Wv16 : Wo16;
    const int K  = 512, Nc = 512;

    __shared__ float s[32][33];
    const int k0 = blockIdx.y * 32, n0 = blockIdx.x * 32;
    const int tx = threadIdx.x & 31, ty = threadIdx.x >> 5;
    #pragma unroll
    for (int q = 0; q < 4; q++)
        s[ty + 8*q][tx] = W[(size_t)(k0 + ty + 8*q) * Nc + n0 + tx];
    __syncthreads();
    for (int o = threadIdx.x; o < 512; o += 256) {
        const int n  = o >> 4;
        const int kp = o & 15;
        __half2 hp = __floats2half2_rn(s[2*kp][n], s[2*kp + 1][n]);
        size_t oi = (size_t)(n0 + n) * (K >> 1) + (k0 >> 1) + kp;
        W16[oi] = *reinterpret_cast<uint32_t*>(&hp);
    }
}

// ============================================================
// fp16 1-pass GEMM: C = A(fp16) @ B16^T (+bias if non-null).
// 64-fp16 k-chunk per stage, 3-stage cp.async pipeline.
// ============================================================
__global__ __launch_bounds__(256, 2)
void gemm_a16_1p_kernel(const uint32_t* __restrict__ A16, const uint32_t* __restrict__ B16,
                        const float* __restrict__ bias, float* __restrict__ C,
                        int Ncols, int K)
{
    extern __shared__ uint32_t smem[];
    const int KUr = K >> 1;
    const int ntiles = KUr >> 5;          // KCHUNK=32 u32 per tile

    const int tid = threadIdx.x;
    const int wid = tid >> 5, lane = tid & 31;
    const int warp_m = wid & 1;
    const int warp_n = wid >> 1;
    const int r  = lane >> 2;
    const int cq = lane & 3;
    const int rowBase = blockIdx.y * 128;
    const int colBase = blockIdx.x * 128;

    const int ldRow = tid >> 3;
    const int ldC16 = tid & 7;

    const int aOffBase = (warp_m * 64 + (lane & 15)) * ROWSTRIDE + ((lane >> 4) << 2);
    const int bOffBase = (warp_n * 32 + (lane & 7) + ((lane >> 4) << 3)) * ROWSTRIDE
                         + (((lane >> 3) & 1) << 2);

    const uint32_t smem_base_addr = (uint32_t)__cvta_generic_to_shared(smem);

    #define PREFETCH2(kt, st) do {                                                    \
        uint32_t* s_ = smem + (st) * STAGE2_U32;                                      \
        _Pragma("unroll")                                                             \
        for (int j = 0; j < 4; j++) {                                                 \
            const int row_ = ldRow + j * 32;                                          \
            const int cu_  = ldC16 * 4;                                               \
            const size_t ao_ = (size_t)(rowBase + row_) * KUr + (kt) + cu_;           \
            const size_t bo_ = (size_t)(colBase + row_) * KUr + (kt) + cu_;           \
            cp_async16(s_ + 0*ARR_U32 + row_*ROWSTRIDE + cu_, A16 + ao_);             \
            cp_async16(s_ + 1*ARR_U32 + row_*ROWSTRIDE + cu_, B16 + bo_);             \
        }                                                                             \
    } while (0)

    float acc[4][4][4];
    #pragma unroll
    for (int a = 0; a < 4; a++)
        #pragma unroll
        for (int b_ = 0; b_ < 4; b_++)
            #pragma unroll
            for (int c = 0; c < 4; c++) acc[a][b_][c] = 0.f;

    PREFETCH2(0, 0);
    cp_commit();
    if (ntiles > 1) {
        PREFETCH2(KCHUNK, 1);
        cp_commit();
    }

    int st = 0;
    for (int t = 0; t < ntiles; t++) {
        if (t + 2 < ntiles) {
            int st2 = st + 2; if (st2 >= NSTAGES) st2 -= NSTAGES;
            PREFETCH2((t + 2) * KCHUNK, st2);
            cp_commit();
        }
        if (t + 2 < ntiles)      cp_wait2();
        else if (t + 1 < ntiles) cp_wait1();
        else                     cp_wait0();
        __syncthreads();

        const uint32_t stage = smem_base_addr + (st * STAGE2_U32) * 4;
        const uint32_t aB  = stage + (0 * ARR_U32 + aOffBase) * 4;
        const uint32_t bB  = stage + (1 * ARR_U32 + bOffBase) * 4;

        #pragma unroll
        for (int ks = 0; ks < 4; ks++) {
            const uint32_t kuB = ks * 8 * 4;
            uint32_t bh[4][2];
            #pragma unroll
            for (int pair = 0; pair < 2; pair++) {
                const uint32_t po = pair * 16 * ROWSTRIDE * 4;
                ldsm_x4(bh[2*pair][0], bh[2*pair][1], bh[2*pair+1][0], bh[2*pair+1][1],
                        bB + po + kuB);
            }
            #pragma unroll
            for (int mt = 0; mt < 4; mt++) {
                const uint32_t mo = mt * 16 * ROWSTRIDE * 4;
                uint32_t a0, a1, a2, a3;
                ldsm_x4(a0, a1, a2, a3, aB + mo + kuB);
                #pragma unroll
                for (int nt = 0; nt < 4; nt++) {
                    float* d = acc[mt][nt];
                    mma_fp16(d[0], d[1], d[2], d[3], a0, a1, a2, a3, bh[nt][0], bh[nt][1]);
                }
            }
        }
        __syncthreads();

        if (++st >= NSTAGES) st = 0;
    }
    #undef PREFETCH2

    #pragma unroll
    for (int mt = 0; mt < 4; mt++) {
        const int row0 = rowBase + warp_m * 64 + mt * 16 + r;
        #pragma unroll
        for (int nt = 0; nt < 4; nt++) {
            const int col = colBase + warp_n * 32 + nt * 8 + 2 * cq;
            float b0v = 0.f, b1v = 0.f;
            if (bias) { b0v = bias[col]; b1v = bias[col + 1]; }
            float2 p0 = make_float2(acc[mt][nt][0] + b0v, acc[mt][nt][1] + b1v);
            float2 p1 = make_float2(acc[mt][nt][2] + b0v, acc[mt][nt][3] + b1v);
            *(float2*)&C[(size_t)row0 * Ncols + col]       = p0;
            *(float2*)&C[(size_t)(row0 + 8) * Ncols + col] = p1;
        }
    }
}

// ============================================================
// sigma + x->fp16 fused: one warp per (b,n) row.
// ============================================================
__global__ __launch_bounds__(256)
void sigma_x16_kernel(const float* __restrict__ x, const float4* __restrict__ Wsig,
                      const float* __restrict__ bsig, float* __restrict__ inv_out,
                      uint32_t* __restrict__ x16)
{
    const int warp = threadIdx.x >> 5;
    const int lane = threadIdx.x & 31;
    const int bn = blockIdx.x * 8 + warp;
    const int b = bn / N;
    const int n = bn % N;

    const float2* xrow = (const float2*)(x + (size_t)bn * D);
    uint32_t* xout = x16 + (size_t)bn * KU512;

    float acc[HEADS];
    #pragma unroll
    for (int h = 0; h < HEADS; h++) acc[h] = 0.f;

    #pragma unroll
    for (int it = 0; it < D / 64; it++) {
        const int p = lane + 32 * it;
        const float2 xv = __ldg(&xrow[p]);
        const float4 wa0 = __ldg(&Wsig[(2*p) * 2 + 0]);
        const float4 wa1 = __ldg(&Wsig[(2*p) * 2 + 1]);
        const float4 wb0 = __ldg(&Wsig[(2*p + 1) * 2 + 0]);
        const float4 wb1 = __ldg(&Wsig[(2*p + 1) * 2 + 1]);
        acc[0] += xv.x * wa0.x + xv.y * wb0.x;
        acc[1] += xv.x * wa0.y + xv.y * wb0.y;
        acc[2] += xv.x * wa0.z + xv.y * wb0.z;
        acc[3] += xv.x * wa0.w + xv.y * wb0.w;
        acc[4] += xv.x * wa1.x + xv.y * wb1.x;
        acc[5] += xv.x * wa1.y + xv.y * wb1.y;
        acc[6] += xv.x * wa1.z + xv.y * wb1.z;
        acc[7] += xv.x * wa1.w + xv.y * wb1.w;
        __half2 hp = __floats2half2_rn(xv.x, xv.y);
        xout[p] = *reinterpret_cast<uint32_t*>(&hp);
    }

    #pragma unroll
    for (int off = 16; off > 0; off >>= 1)
        #pragma unroll
        for (int h = 0; h < HEADS; h++)
            acc[h] += __shfl_xor_sync(0xFFFFFFFFu, acc[h], off);

    if (lane < HEADS) {
        const int h = lane;
        float s = acc[h] + __ldg(&bsig[h]);
        float sig = 1.f / (1.f + expf(-s));
        float denom = expf(sig) + 1.f;
        inv_out[((size_t)b * HEADS + h) * N + n] = 1.f / denom;
    }
}

// ============================================================
// Band kernel — f32x2 Horner, BW=40, 8 rows/thread (256 threads).
// smem window 144 rows. Entry-side extra far terms are true softmax
// mass (no masks needed); exit peels are statically masked so each
// row stops exactly at its center / center+1. Exact analytic Z.
// ============================================================
__global__ __launch_bounds__(256)
void band_kernel(const float* __restrict__ v, const float* __restrict__ inv_arr,
                 unsigned short* __restrict__ a16)
{
    __shared__ float vs[RB + 2 * BW][DH];   // 144 x 64 x 4B = 36.9KB

    const int b  = blockIdx.z;
    const int h  = blockIdx.y;
    const int i0 = blockIdx.x * RB;
    const int tid = threadIdx.x;
    const int lp  = tid & 31;               // dh pair index
    const int g   = tid >> 5;               // 0..7, rows base g*8

    for (int t = tid; t < (RB + 2 * BW) * (DH / 4); t += 256) {
        const int row = t >> 4;
        const int c4  = (t & 15) * 4;
        const int jj  = i0 - BW + row;
        float4 val = make_float4(0.f, 0.f, 0.f, 0.f);
        if (jj >= 0 && jj < N)
            val = __ldg((const float4*)&v[((size_t)(b * N + jj)) * INNER + h * DH + c4]);
        *(float4*)&vs[row][c4] = val;
    }
    __syncthreads();

    const float* invp = inv_arr + ((size_t)b * HEADS + h) * N;
    const int base = i0 + g * 8;
    // local center of row t is g*8 + t + BW

    float rr[8], iv[8];
    uint64_t rr2[8], accL[8], accR[8];
    #pragma unroll
    for (int t = 0; t < 8; t++) {
        iv[t]   = invp[base + t];
        rr[t]   = __expf(-iv[t]);
        rr2[t]  = f32x2_pack(rr[t], rr[t]);
        accL[t] = 0ull;
        accR[t] = 0ull;
    }

    // Left sweep: j ascending from g*8 (center(0)-BW); ends at each center.
    {
        int jl = g * 8;
        #pragma unroll 8
        for (int m = 0; m <= BW; m++) {          // 41 steps, all rows active
            const uint64_t v2 = *(const uint64_t*)&vs[jl][2 * lp];
            #pragma unroll
            for (int t = 0; t < 8; t++) accL[t] = fma2(accL[t], rr2[t], v2);
            jl++;
        }
        #pragma unroll
        for (int m = BW + 1; m < BW + 8; m++) {  // row t active iff t >= m-BW
            const uint64_t v2 = *(const uint64_t*)&vs[jl][2 * lp];
            #pragma unroll
            for (int t = 0; t < 8; t++)
                if (t >= m - BW) accL[t] = fma2(accL[t], rr2[t], v2);
            jl++;
        }
    }

    // Right sweep: j descending from g*8 + 7 + 2*BW (center(7)+BW);
    // ends at each center+1.
    {
        int jl = g * 8 + 7 + 2 * BW;
        #pragma unroll 8
        for (int m = 0; m < BW; m++) {           // 40 steps, all rows active
            const uint64_t v2 = *(const uint64_t*)&vs[jl][2 * lp];
            #pragma unroll
            for (int t = 0; t < 8; t++) accR[t] = fma2(accR[t], rr2[t], v2);
            jl--;
        }
        #pragma unroll
        for (int m = BW; m < BW + 7; m++) {      // row t active iff t <= BW+6-m
            const uint64_t v2 = *(const uint64_t*)&vs[jl][2 * lp];
            #pragma unroll
            for (int t = 0; t < 8; t++)
                if (t <= BW + 6 - m) accR[t] = fma2(accR[t], rr2[t], v2);
            jl--;
        }
    }

    // combine, normalize (exact analytic Z), emit fp16 pair
    #pragma unroll
    for (int t = 0; t < 8; t++) {
        const int i = base + t;
        const float r_ = rr[t];
        const uint64_t sum2 = fma2(rr2[t], accR[t], accL[t]);   // accL + r*accR
        const float Z = (1.f - __expf(-(float)(i + 1) * iv[t])
                         + r_ - __expf(-(float)(N - i) * iv[t])) / (1.f - r_);
        const float zi = 1.f / Z;
        const float2 o = f32x2_unpack(mul2(sum2, f32x2_pack(zi, zi)));

        __half2 hp = __halves2half2(__float2half_rn(o.x), __float2half_rn(o.y));
        const size_t idx = ((size_t)(b * N + i)) * INNER + h * DH + 2 * lp;
        *(uint32_t*)&a16[idx] = *reinterpret_cast<uint32_t*>(&hp);
    }
}

// ============================================================
// Launch: x, W_v, W_sigma, b_sigma, W_out, b_out
// ============================================================
extern "C" void kernel_launch(void* const* d_in, const int* in_sizes, int n_in,
                              void* d_out, int out_size)
{
    const float* x     = (const float*)d_in[0];
    const float* W_v   = (const float*)d_in[1];
    const float* W_sig = (const float*)d_in[2];
    const float* b_sig = (const float*)d_in[3];
    const float* W_out = (const float*)d_in[4];
    const float* b_out = (const float*)d_in[5];
    float* out = (float*)d_out;

    uint32_t *x16, *wvt16, *wot16;
    float *v, *inv;
    unsigned short *a16;
    cudaGetSymbolAddress((void**)&x16, g_x16);
    cudaGetSymbolAddress((void**)&wvt16, g_wvt16);
    cudaGetSymbolAddress((void**)&wot16, g_wot16);
    cudaGetSymbolAddress((void**)&v, g_v);
    cudaGetSymbolAddress((void**)&inv, g_inv);
    cudaGetSymbolAddress((void**)&a16, g_a16);

    static bool attr_set = false;
    if (!attr_set) {
        cudaFuncSetAttribute(gemm_a16_1p_kernel,
                             cudaFuncAttributeMaxDynamicSharedMemorySize,
                             GEMM2_SMEM_BYTES);
        attr_set = true;
    }

    // both weight transposes in ONE launch
    {
        dim3 grid(16, 16, 2);
        convert_both_kernel<<<grid, 256>>>(W_v, wvt16, W_out, wot16);
    }
    // sigma + x->fp16 (fused)
    sigma_x16_kernel<<<M_ROWS / 8, 256>>>(x, (const float4*)W_sig, b_sig, inv, x16);
    // v = x @ W_v  (fp16 1-pass, 3-stage)
    {
        dim3 grid(INNER / 128, M_ROWS / 128);
        gemm_a16_1p_kernel<<<grid, 256, GEMM2_SMEM_BYTES>>>(x16, wvt16, nullptr, v,
                                                            INNER, D);
    }
    // banded prior @ v -> attn fp16
    {
        dim3 grid(N / RB, HEADS, B);
        band_kernel<<<grid, 256>>>(v, inv, a16);
    }
    // out = attn @ W_out + b_out  (fp16 1-pass, 3-stage)
    {
        dim3 grid(D / 128, M_ROWS / 128);
        gemm_a16_1p_kernel<<<grid, 256, GEMM2_SMEM_BYTES>>>((const uint32_t*)a16,
                                                            wot16, b_out, out,
                                                            D, INNER);
    }
}